// round 3
// baseline (speedup 1.0000x reference)
#include <cuda_runtime.h>
#include <cstdint>

#define N_NODES 50000
#define NE      600000
#define D       128

// Scratch (static device globals — no allocations allowed)
__device__ int   g_deg[N_NODES];
__device__ float g_dinv[N_NODES];
__device__ float g_msg[(size_t)N_NODES * D];   // g[i] = dinv[i] * (x[i] @ W)

// ---------------------------------------------------------------------------
// f32x2 packed-FMA helpers (Blackwell FFMA2 — only reachable via PTX)
// ---------------------------------------------------------------------------
__device__ __forceinline__ unsigned long long ffma2(unsigned long long a,
                                                    unsigned long long b,
                                                    unsigned long long c) {
    unsigned long long d;
    asm("fma.rn.f32x2 %0, %1, %2, %3;" : "=l"(d) : "l"(a), "l"(b), "l"(c));
    return d;
}
__device__ __forceinline__ unsigned long long pack2(float x) {
    unsigned long long r;
    asm("mov.b64 %0, {%1, %1};" : "=l"(r) : "f"(x));
    return r;
}

// ---------------------------------------------------------------------------
// K0: deg = 1 (self loop)
// ---------------------------------------------------------------------------
__global__ void k_init_deg() {
    int i = blockIdx.x * blockDim.x + threadIdx.x;
    if (i < N_NODES) g_deg[i] = 1;
}

// K1: in-degree count over destination column (edge_index is int32 — JAX
// default x64-disabled makes the declared int64 actually int32)
__global__ void k_count(const int* __restrict__ col) {
    int e = blockIdx.x * blockDim.x + threadIdx.x;
    if (e < NE) atomicAdd(&g_deg[col[e]], 1);
}

// K2: dinv = rsqrt(deg)
__global__ void k_dinv() {
    int i = blockIdx.x * blockDim.x + threadIdx.x;
    if (i < N_NODES) g_dinv[i] = rsqrtf((float)g_deg[i]);
}

// ---------------------------------------------------------------------------
// K3: g[i] = dinv[i] * (x[i] @ W);  also acc(=d_out)[i] = g[i]  (self-loop term)
// Block: 256 threads, 64 rows/block, register tile 4 rows x 8 cols (4 f32x2 pairs)
// W staged in smem in two k-halves of 64 (keeps static smem at 48KB).
// ---------------------------------------------------------------------------
__global__ __launch_bounds__(256) void k_gemm(const float* __restrict__ x,
                                              const float* __restrict__ W,
                                              float* __restrict__ acc) {
    __shared__ float sW[64 * D];   // 32 KB : W[k_half][col]
    __shared__ float sX[64 * 64];  // 16 KB : x[row][k_half]

    const int t       = threadIdx.x;
    const int rowBase = blockIdx.x * 64;
    const int cg      = t & 15;        // 16 column groups
    const int r0      = (t >> 4) * 4;  // 16 row groups * 4 rows

    unsigned long long c[4][4];
#pragma unroll
    for (int r = 0; r < 4; r++)
#pragma unroll
        for (int j = 0; j < 4; j++) c[r][j] = 0ULL;

    for (int kh = 0; kh < 2; kh++) {
        __syncthreads();
        // stage W rows [kh*64, kh*64+64)
        const float4* W4 = (const float4*)(W + kh * 64 * D);
#pragma unroll
        for (int i = t; i < 64 * D / 4; i += 256) ((float4*)sW)[i] = W4[i];
        // stage x tile [64 rows][64 k]
#pragma unroll
        for (int i = t; i < 64 * 64 / 4; i += 256) {
            int r    = i >> 4;          // 16 float4 per row
            int c4   = i & 15;
            int grow = rowBase + r;
            float4 v = make_float4(0.f, 0.f, 0.f, 0.f);
            if (grow < N_NODES)
                v = *(const float4*)(x + (size_t)grow * D + kh * 64 + c4 * 4);
            ((float4*)sX)[i] = v;
        }
        __syncthreads();

#pragma unroll 16
        for (int k = 0; k < 64; k++) {
            unsigned long long xp[4];
#pragma unroll
            for (int r = 0; r < 4; r++)
                xp[r] = pack2(sX[(r0 + r) * 64 + k]);
            unsigned long long w[4];
#pragma unroll
            for (int j = 0; j < 4; j++) {
                // columns: 2*cg + 32*j  -> conflict-free LDS.64 across the warp
                float2 wv = *(const float2*)(sW + k * D + 2 * cg + 32 * j);
                w[j] = *reinterpret_cast<unsigned long long*>(&wv);
            }
#pragma unroll
            for (int r = 0; r < 4; r++)
#pragma unroll
                for (int j = 0; j < 4; j++)
                    c[r][j] = ffma2(xp[r], w[j], c[r][j]);
        }
    }

    // epilogue: scale by dinv, write g and acc(=d_out)
#pragma unroll
    for (int r = 0; r < 4; r++) {
        int grow = rowBase + r0 + r;
        if (grow >= N_NODES) continue;
        float dv = g_dinv[grow];
#pragma unroll
        for (int j = 0; j < 4; j++) {
            union { unsigned long long u; float2 f; } cv;
            cv.u = c[r][j];
            cv.f.x *= dv;
            cv.f.y *= dv;
            int col = 2 * cg + 32 * j;
            *(float2*)(g_msg + (size_t)grow * D + col) = cv.f;
            *(float2*)(acc + (size_t)grow * D + col)   = cv.f;
        }
    }
}

// ---------------------------------------------------------------------------
// K4: scatter — one warp per edge, atomicAdd(float4*) (16B vector reduction,
// sm_90+ intrinsic; global memory). acc[dst][:] += g[src][:]
// ---------------------------------------------------------------------------
__global__ __launch_bounds__(256) void k_scatter(const int* __restrict__ ei,
                                                 float* __restrict__ acc) {
    int gtid = blockIdx.x * blockDim.x + threadIdx.x;
    int e    = gtid >> 5;
    int lane = gtid & 31;
    if (e >= NE) return;
    int src = ei[e];        // source row
    int dst = ei[NE + e];   // destination col

    float4 v = ((const float4*)(g_msg + (size_t)src * D))[lane];
    float4* p = (float4*)(acc + (size_t)dst * D) + lane;
    atomicAdd(p, v);
}

// ---------------------------------------------------------------------------
// K5: out = dinv * acc + b   (in-place on d_out)
// ---------------------------------------------------------------------------
__global__ __launch_bounds__(256) void k_final(float* __restrict__ out,
                                               const float* __restrict__ b) {
    int idx = blockIdx.x * blockDim.x + threadIdx.x;   // over N*D/4 float4s
    if (idx >= N_NODES * (D / 4)) return;
    int row  = idx / (D / 4);
    int coff = idx % (D / 4);
    float dv = g_dinv[row];
    float4 v  = ((float4*)out)[idx];
    float4 bb = ((const float4*)b)[coff];
    v.x = v.x * dv + bb.x;
    v.y = v.y * dv + bb.y;
    v.z = v.z * dv + bb.z;
    v.w = v.w * dv + bb.w;
    ((float4*)out)[idx] = v;
}

// ---------------------------------------------------------------------------
extern "C" void kernel_launch(void* const* d_in, const int* in_sizes, int n_in,
                              void* d_out, int out_size) {
    const float* x   = (const float*)d_in[0];
    const int*   ei  = (const int*)d_in[1];    // int32 (JAX x64-disabled)
    const float* W   = (const float*)d_in[2];
    const float* b   = (const float*)d_in[3];
    float*       out = (float*)d_out;

    k_init_deg<<<(N_NODES + 255) / 256, 256>>>();
    k_count<<<(NE + 255) / 256, 256>>>(ei + NE);
    k_dinv<<<(N_NODES + 255) / 256, 256>>>();
    k_gemm<<<(N_NODES + 63) / 64, 256>>>(x, W, out);
    k_scatter<<<(NE * 32 + 255) / 256, 256>>>(ei, out);
    k_final<<<(N_NODES * (D / 4) + 255) / 256, 256>>>(out, b);
}

// round 5
// speedup vs baseline: 1.3725x; 1.3725x over previous
#include <cuda_runtime.h>
#include <cstdint>

#define N_NODES 50000
#define NE      600000
#define D       128
#define SCAN_B  512
#define NSCANB  ((N_NODES + SCAN_B - 1) / SCAN_B)   // 98

// Scratch (static device globals — no allocations allowed)
__device__ int   g_deg[N_NODES];
__device__ float g_dinv[N_NODES];
__device__ float g_msg[(size_t)N_NODES * D];   // g[i] = dinv[i] * (x[i] @ W)
__device__ int   g_rowptr[N_NODES + 1];
__device__ int   g_cursor[N_NODES];
__device__ int   g_srcidx[NE];
__device__ int   g_blocksum[128];
__device__ int   g_blockoff[128];

// ---------------------------------------------------------------------------
// f32x2 packed-FMA helpers (Blackwell FFMA2 — only reachable via PTX)
// ---------------------------------------------------------------------------
__device__ __forceinline__ unsigned long long ffma2(unsigned long long a,
                                                    unsigned long long b,
                                                    unsigned long long c) {
    unsigned long long d;
    asm("fma.rn.f32x2 %0, %1, %2, %3;" : "=l"(d) : "l"(a), "l"(b), "l"(c));
    return d;
}
__device__ __forceinline__ unsigned long long pack2(float x) {
    unsigned long long r;
    asm("mov.b64 %0, {%1, %1};" : "=l"(r) : "f"(x));
    return r;
}

// ---------------------------------------------------------------------------
// K0: deg = 0  (edge-only in-degree; self-loop handled analytically)
// ---------------------------------------------------------------------------
__global__ void k_init_deg() {
    int i = blockIdx.x * blockDim.x + threadIdx.x;
    if (i < N_NODES) g_deg[i] = 0;
}

// K1: in-degree count over destination column (edge_index is int32)
__global__ void k_count(const int* __restrict__ col) {
    int e = blockIdx.x * blockDim.x + threadIdx.x;
    if (e < NE) atomicAdd(&g_deg[col[e]], 1);
}

// K2: dinv = rsqrt(deg + 1)   (+1 = self loop)
__global__ void k_dinv() {
    int i = blockIdx.x * blockDim.x + threadIdx.x;
    if (i < N_NODES) g_dinv[i] = rsqrtf((float)(g_deg[i] + 1));
}

// ---------------------------------------------------------------------------
// Two-level exclusive scan of g_deg -> g_rowptr
// ---------------------------------------------------------------------------
__global__ __launch_bounds__(SCAN_B) void k_scan_block() {
    __shared__ int s[SCAN_B];
    int gid = blockIdx.x * SCAN_B + threadIdx.x;
    int v = (gid < N_NODES) ? g_deg[gid] : 0;
    s[threadIdx.x] = v;
    __syncthreads();
#pragma unroll
    for (int off = 1; off < SCAN_B; off <<= 1) {
        int t = (threadIdx.x >= off) ? s[threadIdx.x - off] : 0;
        __syncthreads();
        s[threadIdx.x] += t;
        __syncthreads();
    }
    if (gid < N_NODES) g_rowptr[gid] = s[threadIdx.x] - v;   // exclusive-in-block
    if (threadIdx.x == SCAN_B - 1) g_blocksum[blockIdx.x] = s[SCAN_B - 1];
}

__global__ __launch_bounds__(128) void k_scan_top() {
    __shared__ int s[128];
    int v = (threadIdx.x < NSCANB) ? g_blocksum[threadIdx.x] : 0;
    s[threadIdx.x] = v;
    __syncthreads();
#pragma unroll
    for (int off = 1; off < 128; off <<= 1) {
        int t = (threadIdx.x >= off) ? s[threadIdx.x - off] : 0;
        __syncthreads();
        s[threadIdx.x] += t;
        __syncthreads();
    }
    g_blockoff[threadIdx.x] = s[threadIdx.x] - v;            // exclusive
}

__global__ __launch_bounds__(256) void k_scan_fix() {
    int gid = blockIdx.x * blockDim.x + threadIdx.x;
    if (gid < N_NODES) {
        int rp = g_rowptr[gid] + g_blockoff[gid / SCAN_B];
        g_rowptr[gid] = rp;
        g_cursor[gid] = rp;
    }
    if (gid == 0) g_rowptr[N_NODES] = NE;
}

// K: CSR fill — slot each edge's src under its dst
__global__ __launch_bounds__(256) void k_fill(const int* __restrict__ ei) {
    int e = blockIdx.x * blockDim.x + threadIdx.x;
    if (e >= NE) return;
    int src = ei[e];
    int dst = ei[NE + e];
    int pos = atomicAdd(&g_cursor[dst], 1);
    g_srcidx[pos] = src;
}

// ---------------------------------------------------------------------------
// GEMM: g[i] = dinv[i] * (x[i] @ W)   (writes g_msg only)
// ---------------------------------------------------------------------------
__global__ __launch_bounds__(256) void k_gemm(const float* __restrict__ x,
                                              const float* __restrict__ W) {
    __shared__ float sW[64 * D];   // 32 KB
    __shared__ float sX[64 * 64];  // 16 KB

    const int t       = threadIdx.x;
    const int rowBase = blockIdx.x * 64;
    const int cg      = t & 15;
    const int r0      = (t >> 4) * 4;

    unsigned long long c[4][4];
#pragma unroll
    for (int r = 0; r < 4; r++)
#pragma unroll
        for (int j = 0; j < 4; j++) c[r][j] = 0ULL;

    for (int kh = 0; kh < 2; kh++) {
        __syncthreads();
        const float4* W4 = (const float4*)(W + kh * 64 * D);
#pragma unroll
        for (int i = t; i < 64 * D / 4; i += 256) ((float4*)sW)[i] = W4[i];
#pragma unroll
        for (int i = t; i < 64 * 64 / 4; i += 256) {
            int r    = i >> 4;
            int c4   = i & 15;
            int grow = rowBase + r;
            float4 v = make_float4(0.f, 0.f, 0.f, 0.f);
            if (grow < N_NODES)
                v = *(const float4*)(x + (size_t)grow * D + kh * 64 + c4 * 4);
            ((float4*)sX)[i] = v;
        }
        __syncthreads();

#pragma unroll 16
        for (int k = 0; k < 64; k++) {
            unsigned long long xp[4];
#pragma unroll
            for (int r = 0; r < 4; r++)
                xp[r] = pack2(sX[(r0 + r) * 64 + k]);
            unsigned long long w[4];
#pragma unroll
            for (int j = 0; j < 4; j++) {
                float2 wv = *(const float2*)(sW + k * D + 2 * cg + 32 * j);
                w[j] = *reinterpret_cast<unsigned long long*>(&wv);
            }
#pragma unroll
            for (int r = 0; r < 4; r++)
#pragma unroll
                for (int j = 0; j < 4; j++)
                    c[r][j] = ffma2(xp[r], w[j], c[r][j]);
        }
    }

#pragma unroll
    for (int r = 0; r < 4; r++) {
        int grow = rowBase + r0 + r;
        if (grow >= N_NODES) continue;
        float dv = g_dinv[grow];
#pragma unroll
        for (int j = 0; j < 4; j++) {
            union { unsigned long long u; float2 f; } cv;
            cv.u = c[r][j];
            cv.f.x *= dv;
            cv.f.y *= dv;
            *(float2*)(g_msg + (size_t)grow * D + 2 * cg + 32 * j) = cv.f;
        }
    }
}

// ---------------------------------------------------------------------------
// Gather: one warp per destination node.
// out[i] = dinv[i] * (sum_{p in CSR(i)} g[src_p] + g[i]) + b
// Lanes hold float4 columns; 2-way edge unroll for MLP.
// ---------------------------------------------------------------------------
__global__ __launch_bounds__(256) void k_gather(float* __restrict__ out,
                                                const float* __restrict__ b) {
    int w    = (blockIdx.x * 256 + threadIdx.x) >> 5;
    int lane = threadIdx.x & 31;
    if (w >= N_NODES) return;

    const float4* gm = (const float4*)g_msg;
    float4 acc = gm[(size_t)w * 32 + lane];      // self loop
    int p  = g_rowptr[w];
    int pe = g_rowptr[w + 1];

    for (; p + 1 < pe; p += 2) {
        int s0 = g_srcidx[p];
        int s1 = g_srcidx[p + 1];
        float4 a = gm[(size_t)s0 * 32 + lane];
        float4 c = gm[(size_t)s1 * 32 + lane];
        acc.x += a.x + c.x;
        acc.y += a.y + c.y;
        acc.z += a.z + c.z;
        acc.w += a.w + c.w;
    }
    if (p < pe) {
        int s0 = g_srcidx[p];
        float4 a = gm[(size_t)s0 * 32 + lane];
        acc.x += a.x; acc.y += a.y; acc.z += a.z; acc.w += a.w;
    }

    float dv  = g_dinv[w];
    float4 bb = ((const float4*)b)[lane];
    float4 o;
    o.x = acc.x * dv + bb.x;
    o.y = acc.y * dv + bb.y;
    o.z = acc.z * dv + bb.z;
    o.w = acc.w * dv + bb.w;
    ((float4*)out)[(size_t)w * 32 + lane] = o;
}

// ---------------------------------------------------------------------------
extern "C" void kernel_launch(void* const* d_in, const int* in_sizes, int n_in,
                              void* d_out, int out_size) {
    const float* x   = (const float*)d_in[0];
    const int*   ei  = (const int*)d_in[1];    // int32 (JAX x64-disabled)
    const float* W   = (const float*)d_in[2];
    const float* b   = (const float*)d_in[3];
    float*       out = (float*)d_out;

    k_init_deg<<<(N_NODES + 255) / 256, 256>>>();
    k_count<<<(NE + 255) / 256, 256>>>(ei + NE);
    k_dinv<<<(N_NODES + 255) / 256, 256>>>();
    k_scan_block<<<NSCANB, SCAN_B>>>();
    k_scan_top<<<1, 128>>>();
    k_scan_fix<<<(N_NODES + 255) / 256, 256>>>();
    k_fill<<<(NE + 255) / 256, 256>>>(ei);
    k_gemm<<<(N_NODES + 63) / 64, 256>>>(x, W);
    k_gather<<<(N_NODES * 32 + 255) / 256, 256>>>(out, b);
}

// round 7
// speedup vs baseline: 1.4395x; 1.0487x over previous
#include <cuda_runtime.h>
#include <cuda_bf16.h>
#include <cstdint>

#define N_NODES 50000
#define NE      600000
#define D       128
#define SCAN_B  512
#define NSCANB  ((N_NODES + SCAN_B - 1) / SCAN_B)   // 98

// ---------------------------------------------------------------------------
// Scratch (static device globals — no allocations allowed)
// ---------------------------------------------------------------------------
__device__ int   g_deg[N_NODES];
__device__ float g_dinv[N_NODES];
__device__ float g_msg[(size_t)N_NODES * D];   // g[i] = dinv[i] * (x[i] @ W)
__device__ int   g_rowptr[N_NODES + 1];
__device__ int   g_cursor[N_NODES];
__device__ int   g_srcidx[NE];
__device__ int   g_blocksum[128];
__device__ int   g_blockoff[128];
// W in mma.sync B-fragment layout: [kstep 8][ntile 16][lane 32] uint2, hi & lo
__device__ uint2 g_Bhi[8 * 16 * 32];
__device__ uint2 g_Blo[8 * 16 * 32];

// ---------------------------------------------------------------------------
// bf16 helpers
// ---------------------------------------------------------------------------
__device__ __forceinline__ uint32_t bfpack(float a, float b) {
    __nv_bfloat162 h = __floats2bfloat162_rn(a, b);
    return *(uint32_t*)&h;
}
// hi = bf16(v); returns packed hi, writes residual floats
__device__ __forceinline__ uint32_t bfhi_lo(float a, float b, float& ra, float& rb) {
    __nv_bfloat162 h = __floats2bfloat162_rn(a, b);
    ra = a - __bfloat162float(h.x);
    rb = b - __bfloat162float(h.y);
    return *(uint32_t*)&h;
}

#define MMA16816(c, a0, a1, a2, a3, b0, b1)                                    \
    asm volatile(                                                              \
        "mma.sync.aligned.m16n8k16.row.col.f32.bf16.bf16.f32 "                 \
        "{%0,%1,%2,%3}, {%4,%5,%6,%7}, {%8,%9}, {%0,%1,%2,%3};"                \
        : "+f"((c)[0]), "+f"((c)[1]), "+f"((c)[2]), "+f"((c)[3])               \
        : "r"(a0), "r"(a1), "r"(a2), "r"(a3), "r"(b0), "r"(b1))

// ---------------------------------------------------------------------------
// K0/K1: degree
// ---------------------------------------------------------------------------
__global__ void k_init_deg() {
    int i = blockIdx.x * blockDim.x + threadIdx.x;
    if (i < N_NODES) g_deg[i] = 0;
}
__global__ void k_count(const int* __restrict__ col) {
    int e = blockIdx.x * blockDim.x + threadIdx.x;
    if (e < NE) atomicAdd(&g_deg[col[e]], 1);
}

// ---------------------------------------------------------------------------
// Two-level exclusive scan of g_deg -> g_rowptr  (+ fused dinv)
// ---------------------------------------------------------------------------
__global__ __launch_bounds__(SCAN_B) void k_scan_block() {
    __shared__ int s[SCAN_B];
    int gid = blockIdx.x * SCAN_B + threadIdx.x;
    int v = (gid < N_NODES) ? g_deg[gid] : 0;
    if (gid < N_NODES) g_dinv[gid] = rsqrtf((float)(v + 1));   // fused
    s[threadIdx.x] = v;
    __syncthreads();
#pragma unroll
    for (int off = 1; off < SCAN_B; off <<= 1) {
        int t = (threadIdx.x >= off) ? s[threadIdx.x - off] : 0;
        __syncthreads();
        s[threadIdx.x] += t;
        __syncthreads();
    }
    if (gid < N_NODES) g_rowptr[gid] = s[threadIdx.x] - v;
    if (threadIdx.x == SCAN_B - 1) g_blocksum[blockIdx.x] = s[SCAN_B - 1];
}
__global__ __launch_bounds__(128) void k_scan_top() {
    __shared__ int s[128];
    int v = (threadIdx.x < NSCANB) ? g_blocksum[threadIdx.x] : 0;
    s[threadIdx.x] = v;
    __syncthreads();
#pragma unroll
    for (int off = 1; off < 128; off <<= 1) {
        int t = (threadIdx.x >= off) ? s[threadIdx.x - off] : 0;
        __syncthreads();
        s[threadIdx.x] += t;
        __syncthreads();
    }
    g_blockoff[threadIdx.x] = s[threadIdx.x] - v;
}
__global__ __launch_bounds__(256) void k_scan_fix() {
    int gid = blockIdx.x * blockDim.x + threadIdx.x;
    if (gid < N_NODES) {
        int rp = g_rowptr[gid] + g_blockoff[gid / SCAN_B];
        g_rowptr[gid] = rp;
        g_cursor[gid] = rp;
    }
    if (gid == 0) g_rowptr[N_NODES] = NE;
}
__global__ __launch_bounds__(256) void k_fill(const int* __restrict__ ei) {
    int e = blockIdx.x * blockDim.x + threadIdx.x;
    if (e >= NE) return;
    int pos = atomicAdd(&g_cursor[ei[NE + e]], 1);
    g_srcidx[pos] = ei[e];
}

// ---------------------------------------------------------------------------
// prepW: W[k][n] -> B-fragment layout for mma.m16n8k16 (row.col):
//   b0 = {W[16s+2t  ][8j+g], W[16s+2t+1][8j+g]}
//   b1 = {W[16s+8+2t][8j+g], W[16s+8+2t+1][8j+g]}
// slot index = ((s*16 + j)*32 + lane)
// ---------------------------------------------------------------------------
__global__ __launch_bounds__(256) void k_prepW(const float* __restrict__ W) {
    for (int slot = threadIdx.x; slot < 8 * 16 * 32; slot += 256) {
        int l = slot & 31;
        int j = (slot >> 5) & 15;
        int s = slot >> 9;
        int g = l >> 2, t = l & 3;
        int n  = 8 * j + g;
        int k0 = 16 * s + 2 * t;
        float w00 = W[(k0 + 0) * D + n];
        float w01 = W[(k0 + 1) * D + n];
        float w10 = W[(k0 + 8) * D + n];
        float w11 = W[(k0 + 9) * D + n];
        float r00, r01, r10, r11;
        uint2 hi, lo;
        hi.x = bfhi_lo(w00, w01, r00, r01);
        hi.y = bfhi_lo(w10, w11, r10, r11);
        lo.x = bfpack(r00, r01);
        lo.y = bfpack(r10, r11);
        g_Bhi[slot] = hi;
        g_Blo[slot] = lo;
    }
}

// ---------------------------------------------------------------------------
// GEMM via mma.sync bf16x3: g[i] = dinv[i] * (x[i] @ W)
// 128 threads / 4 warps, 64 rows per block. Warp w: rows 16w..16w+15.
// Per warp: 8 ksteps x 16 ntiles x 3 HMMA. A converted in regs from smem x.
// ---------------------------------------------------------------------------
#define XS 132   // padded row stride (floats); 16B-aligned, <=2-way LDS conflicts
__global__ __launch_bounds__(128) void k_gemm_mma(const float* __restrict__ x) {
    __shared__ float sX[64 * XS];

    const int tid = threadIdx.x;
    const int w   = tid >> 5;
    const int l   = tid & 31;
    const int g   = l >> 2, t = l & 3;
    const int base = blockIdx.x * 64;

    // stage x[base .. base+64) rows, fp32, coalesced
    for (int i = tid; i < 64 * 32; i += 128) {     // 32 float4 per row
        int r  = i >> 5;
        int c4 = i & 31;
        float4 v = make_float4(0.f, 0.f, 0.f, 0.f);
        if (base + r < N_NODES)
            v = ((const float4*)(x + (size_t)(base + r) * D))[c4];
        *(float4*)(sX + r * XS + c4 * 4) = v;
    }
    __syncthreads();

    float c[16][4];
#pragma unroll
    for (int j = 0; j < 16; j++)
#pragma unroll
        for (int q = 0; q < 4; q++) c[j][q] = 0.f;

    const int r0 = 16 * w + g;          // my low row in the block tile
#pragma unroll
    for (int s = 0; s < 8; s++) {
        // A fragments from smem fp32, hi/lo split
        const float* a0 = sX + r0 * XS + 16 * s + 2 * t;
        const float* a1 = a0 + 8 * XS;
        float2 v00 = *(const float2*)a0;        // row g,   k0..k0+1
        float2 v01 = *(const float2*)(a0 + 8);  // row g,   k0+8..9
        float2 v10 = *(const float2*)a1;        // row g+8, k0..k0+1
        float2 v11 = *(const float2*)(a1 + 8);  // row g+8, k0+8..9
        float q00x, q00y, q10x, q10y, q01x, q01y, q11x, q11y;
        uint32_t ah0 = bfhi_lo(v00.x, v00.y, q00x, q00y);
        uint32_t ah1 = bfhi_lo(v10.x, v10.y, q10x, q10y);
        uint32_t ah2 = bfhi_lo(v01.x, v01.y, q01x, q01y);
        uint32_t ah3 = bfhi_lo(v11.x, v11.y, q11x, q11y);
        uint32_t al0 = bfpack(q00x, q00y);
        uint32_t al1 = bfpack(q10x, q10y);
        uint32_t al2 = bfpack(q01x, q01y);
        uint32_t al3 = bfpack(q11x, q11y);

        const uint2* bh = g_Bhi + (s * 16) * 32 + l;
        const uint2* bl = g_Blo + (s * 16) * 32 + l;
#pragma unroll
        for (int j = 0; j < 16; j++) {
            uint2 B = bh[j * 32];
            uint2 Bl = bl[j * 32];
            MMA16816(c[j], ah0, ah1, ah2, ah3, B.x,  B.y);   // hi*hi
            MMA16816(c[j], al0, al1, al2, al3, B.x,  B.y);   // lo*hi
            MMA16816(c[j], ah0, ah1, ah2, ah3, Bl.x, Bl.y);  // hi*lo
        }
    }

    // epilogue: scale by dinv, store to g_msg
    int R0 = base + r0;
    int R1 = R0 + 8;
    float d0 = (R0 < N_NODES) ? g_dinv[R0] : 0.f;
    float d1 = (R1 < N_NODES) ? g_dinv[R1] : 0.f;
#pragma unroll
    for (int j = 0; j < 16; j++) {
        int col = 8 * j + 2 * t;
        if (R0 < N_NODES) {
            float2 v = make_float2(c[j][0] * d0, c[j][1] * d0);
            *(float2*)(g_msg + (size_t)R0 * D + col) = v;
        }
        if (R1 < N_NODES) {
            float2 v = make_float2(c[j][2] * d1, c[j][3] * d1);
            *(float2*)(g_msg + (size_t)R1 * D + col) = v;
        }
    }
}

// ---------------------------------------------------------------------------
// Gather: one warp per destination node.
// out[i] = dinv[i] * (sum_{p in CSR(i)} g[src_p] + g[i]) + b
// ---------------------------------------------------------------------------
__global__ __launch_bounds__(256) void k_gather(float* __restrict__ out,
                                                const float* __restrict__ b) {
    int w    = (blockIdx.x * 256 + threadIdx.x) >> 5;
    int lane = threadIdx.x & 31;
    if (w >= N_NODES) return;

    const float4* gm = (const float4*)g_msg;
    float4 acc = gm[(size_t)w * 32 + lane];      // self loop
    int p  = g_rowptr[w];
    int pe = g_rowptr[w + 1];

    for (; p + 1 < pe; p += 2) {
        int s0 = g_srcidx[p];
        int s1 = g_srcidx[p + 1];
        float4 a = gm[(size_t)s0 * 32 + lane];
        float4 c = gm[(size_t)s1 * 32 + lane];
        acc.x += a.x + c.x;
        acc.y += a.y + c.y;
        acc.z += a.z + c.z;
        acc.w += a.w + c.w;
    }
    if (p < pe) {
        int s0 = g_srcidx[p];
        float4 a = gm[(size_t)s0 * 32 + lane];
        acc.x += a.x; acc.y += a.y; acc.z += a.z; acc.w += a.w;
    }

    float dv  = g_dinv[w];
    float4 bb = ((const float4*)b)[lane];
    float4 o;
    o.x = acc.x * dv + bb.x;
    o.y = acc.y * dv + bb.y;
    o.z = acc.z * dv + bb.z;
    o.w = acc.w * dv + bb.w;
    ((float4*)out)[(size_t)w * 32 + lane] = o;
}

// ---------------------------------------------------------------------------
extern "C" void kernel_launch(void* const* d_in, const int* in_sizes, int n_in,
                              void* d_out, int out_size) {
    const float* x   = (const float*)d_in[0];
    const int*   ei  = (const int*)d_in[1];    // int32 (JAX x64-disabled)
    const float* W   = (const float*)d_in[2];
    const float* b   = (const float*)d_in[3];
    float*       out = (float*)d_out;

    k_init_deg<<<(N_NODES + 255) / 256, 256>>>();
    k_count<<<(NE + 255) / 256, 256>>>(ei + NE);
    k_prepW<<<1, 256>>>(W);
    k_scan_block<<<NSCANB, SCAN_B>>>();
    k_scan_top<<<1, 128>>>();
    k_scan_fix<<<(N_NODES + 255) / 256, 256>>>();
    k_fill<<<(NE + 255) / 256, 256>>>(ei);
    k_gemm_mma<<<(N_NODES + 63) / 64, 128>>>(x);
    k_gather<<<(N_NODES * 32 + 255) / 256, 256>>>(out, b);
}

// round 8
// speedup vs baseline: 1.5036x; 1.0446x over previous
#include <cuda_runtime.h>
#include <cuda_bf16.h>
#include <cstdint>

#define N_NODES 50000
#define NE      600000
#define D       128
#define SCAN_B  512
#define NSCANB  ((N_NODES + SCAN_B - 1) / SCAN_B)   // 98
#define CNT_BLK ((NE + 255) / 256)                   // 2344

// ---------------------------------------------------------------------------
// Scratch (static device globals — no allocations allowed)
// ---------------------------------------------------------------------------
__device__ int   g_deg[N_NODES];
__device__ float g_dinv[N_NODES];
__device__ float g_msg[(size_t)N_NODES * D];   // g[i] = dinv[i] * (x[i] @ W)
__device__ int   g_rowptr[N_NODES + 1];
__device__ int   g_cursor[N_NODES];
__device__ int   g_srcidx[NE];
__device__ int   g_blocksum[128];
// W in mma.sync B-fragment layout: [kstep 8][ntile 16][lane 32] uint2, hi & lo
__device__ uint2 g_Bhi[8 * 16 * 32];
__device__ uint2 g_Blo[8 * 16 * 32];

// ---------------------------------------------------------------------------
// bf16 helpers
// ---------------------------------------------------------------------------
__device__ __forceinline__ uint32_t bfpack(float a, float b) {
    __nv_bfloat162 h = __floats2bfloat162_rn(a, b);
    return *(uint32_t*)&h;
}
__device__ __forceinline__ uint32_t bfhi_lo(float a, float b, float& ra, float& rb) {
    __nv_bfloat162 h = __floats2bfloat162_rn(a, b);
    ra = a - __bfloat162float(h.x);
    rb = b - __bfloat162float(h.y);
    return *(uint32_t*)&h;
}

#define MMA16816(c, a0, a1, a2, a3, b0, b1)                                    \
    asm volatile(                                                              \
        "mma.sync.aligned.m16n8k16.row.col.f32.bf16.bf16.f32 "                 \
        "{%0,%1,%2,%3}, {%4,%5,%6,%7}, {%8,%9}, {%0,%1,%2,%3};"                \
        : "+f"((c)[0]), "+f"((c)[1]), "+f"((c)[2]), "+f"((c)[3])               \
        : "r"(a0), "r"(a1), "r"(a2), "r"(a3), "r"(b0), "r"(b1))

// ---------------------------------------------------------------------------
// L1: zero degree
// ---------------------------------------------------------------------------
__global__ void k_init_deg() {
    int i = blockIdx.x * blockDim.x + threadIdx.x;
    if (i < N_NODES) g_deg[i] = 0;
}

// ---------------------------------------------------------------------------
// L2 (fused): blocks [0, CNT_BLK) count in-degree; block CNT_BLK preps W frags
// ---------------------------------------------------------------------------
__global__ __launch_bounds__(256) void k_count_prep(const int* __restrict__ ei,
                                                    const float* __restrict__ W) {
    if (blockIdx.x < CNT_BLK) {
        int e = blockIdx.x * 256 + threadIdx.x;
        if (e < NE) atomicAdd(&g_deg[ei[NE + e]], 1);
        return;
    }
    // prepW: W[k][n] -> B-fragment layout for mma.m16n8k16 (row.col)
    for (int slot = threadIdx.x; slot < 8 * 16 * 32; slot += 256) {
        int l = slot & 31;
        int j = (slot >> 5) & 15;
        int s = slot >> 9;
        int g = l >> 2, t = l & 3;
        int n  = 8 * j + g;
        int k0 = 16 * s + 2 * t;
        float w00 = W[(k0 + 0) * D + n];
        float w01 = W[(k0 + 1) * D + n];
        float w10 = W[(k0 + 8) * D + n];
        float w11 = W[(k0 + 9) * D + n];
        float r00, r01, r10, r11;
        uint2 hi, lo;
        hi.x = bfhi_lo(w00, w01, r00, r01);
        hi.y = bfhi_lo(w10, w11, r10, r11);
        lo.x = bfpack(r00, r01);
        lo.y = bfpack(r10, r11);
        g_Bhi[slot] = hi;
        g_Blo[slot] = lo;
    }
}

// ---------------------------------------------------------------------------
// L3: block-level exclusive scan of g_deg (+ fused dinv)
// ---------------------------------------------------------------------------
__global__ __launch_bounds__(SCAN_B) void k_scan_block() {
    __shared__ int s[SCAN_B];
    int gid = blockIdx.x * SCAN_B + threadIdx.x;
    int v = (gid < N_NODES) ? g_deg[gid] : 0;
    if (gid < N_NODES) g_dinv[gid] = rsqrtf((float)(v + 1));   // fused
    s[threadIdx.x] = v;
    __syncthreads();
#pragma unroll
    for (int off = 1; off < SCAN_B; off <<= 1) {
        int t = (threadIdx.x >= off) ? s[threadIdx.x - off] : 0;
        __syncthreads();
        s[threadIdx.x] += t;
        __syncthreads();
    }
    if (gid < N_NODES) g_rowptr[gid] = s[threadIdx.x] - v;
    if (threadIdx.x == SCAN_B - 1) g_blocksum[blockIdx.x] = s[SCAN_B - 1];
}

// ---------------------------------------------------------------------------
// L5 (fused top+fix): add cross-block offsets, init cursor
// ---------------------------------------------------------------------------
__global__ __launch_bounds__(256) void k_scan_fix() {
    __shared__ int ss[128];
    int tid = threadIdx.x;
    int gid = blockIdx.x * 256 + tid;
    if (tid < 128) ss[tid] = (tid < NSCANB) ? g_blocksum[tid] : 0;
    __syncthreads();
    if (gid < N_NODES) {
        int blk = gid / SCAN_B;
        int off = 0;
        for (int i = 0; i < blk; i++) off += ss[i];
        int rp = g_rowptr[gid] + off;
        g_rowptr[gid] = rp;
        g_cursor[gid] = rp;
    }
    if (gid == 0) g_rowptr[N_NODES] = NE;
}

// L6: CSR fill
__global__ __launch_bounds__(256) void k_fill(const int* __restrict__ ei) {
    int e = blockIdx.x * blockDim.x + threadIdx.x;
    if (e >= NE) return;
    int pos = atomicAdd(&g_cursor[ei[NE + e]], 1);
    g_srcidx[pos] = ei[e];
}

// ---------------------------------------------------------------------------
// L4: GEMM via mma.sync bf16x3: g[i] = dinv[i] * (x[i] @ W)
// 128 threads / 4 warps, 64 rows per block. Warp w: rows 16w..16w+15.
// ---------------------------------------------------------------------------
#define XS 132
__global__ __launch_bounds__(128) void k_gemm_mma(const float* __restrict__ x) {
    __shared__ float sX[64 * XS];

    const int tid = threadIdx.x;
    const int w   = tid >> 5;
    const int l   = tid & 31;
    const int g   = l >> 2, t = l & 3;
    const int base = blockIdx.x * 64;

    for (int i = tid; i < 64 * 32; i += 128) {
        int r  = i >> 5;
        int c4 = i & 31;
        float4 v = make_float4(0.f, 0.f, 0.f, 0.f);
        if (base + r < N_NODES)
            v = ((const float4*)(x + (size_t)(base + r) * D))[c4];
        *(float4*)(sX + r * XS + c4 * 4) = v;
    }
    __syncthreads();

    float c[16][4];
#pragma unroll
    for (int j = 0; j < 16; j++)
#pragma unroll
        for (int q = 0; q < 4; q++) c[j][q] = 0.f;

    const int r0 = 16 * w + g;
#pragma unroll
    for (int s = 0; s < 8; s++) {
        const float* a0 = sX + r0 * XS + 16 * s + 2 * t;
        const float* a1 = a0 + 8 * XS;
        float2 v00 = *(const float2*)a0;
        float2 v01 = *(const float2*)(a0 + 8);
        float2 v10 = *(const float2*)a1;
        float2 v11 = *(const float2*)(a1 + 8);
        float q00x, q00y, q10x, q10y, q01x, q01y, q11x, q11y;
        uint32_t ah0 = bfhi_lo(v00.x, v00.y, q00x, q00y);
        uint32_t ah1 = bfhi_lo(v10.x, v10.y, q10x, q10y);
        uint32_t ah2 = bfhi_lo(v01.x, v01.y, q01x, q01y);
        uint32_t ah3 = bfhi_lo(v11.x, v11.y, q11x, q11y);
        uint32_t al0 = bfpack(q00x, q00y);
        uint32_t al1 = bfpack(q10x, q10y);
        uint32_t al2 = bfpack(q01x, q01y);
        uint32_t al3 = bfpack(q11x, q11y);

        const uint2* bh = g_Bhi + (s * 16) * 32 + l;
        const uint2* bl = g_Blo + (s * 16) * 32 + l;
#pragma unroll
        for (int j = 0; j < 16; j++) {
            uint2 B  = bh[j * 32];
            uint2 Bl = bl[j * 32];
            MMA16816(c[j], ah0, ah1, ah2, ah3, B.x,  B.y);   // hi*hi
            MMA16816(c[j], al0, al1, al2, al3, B.x,  B.y);   // lo*hi
            MMA16816(c[j], ah0, ah1, ah2, ah3, Bl.x, Bl.y);  // hi*lo
        }
    }

    int R0 = base + r0;
    int R1 = R0 + 8;
    float d0 = (R0 < N_NODES) ? g_dinv[R0] : 0.f;
    float d1 = (R1 < N_NODES) ? g_dinv[R1] : 0.f;
#pragma unroll
    for (int j = 0; j < 16; j++) {
        int col = 8 * j + 2 * t;
        if (R0 < N_NODES)
            *(float2*)(g_msg + (size_t)R0 * D + col) =
                make_float2(c[j][0] * d0, c[j][1] * d0);
        if (R1 < N_NODES)
            *(float2*)(g_msg + (size_t)R1 * D + col) =
                make_float2(c[j][2] * d1, c[j][3] * d1);
    }
}

// ---------------------------------------------------------------------------
// L7: Gather — one warp per destination node, 4-way unroll, .cg loads
// out[i] = dinv[i] * (sum_{p in CSR(i)} g[src_p] + g[i]) + b
// ---------------------------------------------------------------------------
__global__ __launch_bounds__(256) void k_gather(float* __restrict__ out,
                                                const float* __restrict__ b) {
    int w    = (blockIdx.x * 256 + threadIdx.x) >> 5;
    int lane = threadIdx.x & 31;
    if (w >= N_NODES) return;

    const float4* gm = (const float4*)g_msg;
    float4 acc = __ldcg(gm + (size_t)w * 32 + lane);   // self loop
    int p  = g_rowptr[w];
    int pe = g_rowptr[w + 1];

    for (; p + 3 < pe; p += 4) {
        int s0 = g_srcidx[p];
        int s1 = g_srcidx[p + 1];
        int s2 = g_srcidx[p + 2];
        int s3 = g_srcidx[p + 3];
        float4 a0 = __ldcg(gm + (size_t)s0 * 32 + lane);
        float4 a1 = __ldcg(gm + (size_t)s1 * 32 + lane);
        float4 a2 = __ldcg(gm + (size_t)s2 * 32 + lane);
        float4 a3 = __ldcg(gm + (size_t)s3 * 32 + lane);
        acc.x += (a0.x + a1.x) + (a2.x + a3.x);
        acc.y += (a0.y + a1.y) + (a2.y + a3.y);
        acc.z += (a0.z + a1.z) + (a2.z + a3.z);
        acc.w += (a0.w + a1.w) + (a2.w + a3.w);
    }
    for (; p < pe; p++) {
        int s0 = g_srcidx[p];
        float4 a = __ldcg(gm + (size_t)s0 * 32 + lane);
        acc.x += a.x; acc.y += a.y; acc.z += a.z; acc.w += a.w;
    }

    float dv  = g_dinv[w];
    float4 bb = ((const float4*)b)[lane];
    float4 o;
    o.x = acc.x * dv + bb.x;
    o.y = acc.y * dv + bb.y;
    o.z = acc.z * dv + bb.z;
    o.w = acc.w * dv + bb.w;
    ((float4*)out)[(size_t)w * 32 + lane] = o;
}

// ---------------------------------------------------------------------------
extern "C" void kernel_launch(void* const* d_in, const int* in_sizes, int n_in,
                              void* d_out, int out_size) {
    const float* x   = (const float*)d_in[0];
    const int*   ei  = (const int*)d_in[1];    // int32 (JAX x64-disabled)
    const float* W   = (const float*)d_in[2];
    const float* b   = (const float*)d_in[3];
    float*       out = (float*)d_out;

    k_init_deg<<<(N_NODES + 255) / 256, 256>>>();                 // 1
    k_count_prep<<<CNT_BLK + 1, 256>>>(ei, W);                    // 2
    k_scan_block<<<NSCANB, SCAN_B>>>();                           // 3
    k_gemm_mma<<<(N_NODES + 63) / 64, 128>>>(x);                  // 4 <- profiled
    k_scan_fix<<<(N_NODES + 255) / 256, 256>>>();                 // 5
    k_fill<<<(NE + 255) / 256, 256>>>(ei);                        // 6
    k_gather<<<(N_NODES * 32 + 255) / 256, 256>>>(out, b);        // 7
}